// round 16
// baseline (speedup 1.0000x reference)
#include <cuda_runtime.h>
#include <cstdint>

// Problem constants
#define NB   64
#define NT   2048
#define EMBD 32
#define HID  256
#define KTOT 288
#define CSIZE  8             // cluster size = unit slices (producers per group)
#define BSLICE 16            // batch groups (one cluster each)
#define NCTA  128
#define UPC   32             // units per CTA
#define NROWS 128            // 4 gates x 32 units
#define BPC   4              // batches per CTA
#define NTHREADS 256         // 4 k-segments x (32 rg x 2 bq)
#define NSEG 4
#define SEGK 64

#define WJ   292             // j stride (floats)
#define WRG  1188            // rg stride; %32==4
#define ZPAD 296             // z row stride; %32==8
#define ZBUF (BPC * ZPAD)    // 1184 floats per z buffer
#define GSTR 9
#define GSEG (NROWS * GSTR)  // 1152

// SMEM float offsets
#define W_F   0
// W size = 31*WRG + 3*WJ + KTOT = 37992 -> round to 38000
#define Z_F   38000                     // [2][BPC][ZPAD]
#define GP_F  (Z_F + 2 * ZBUF)          // 40368
#define BS_F  (GP_F + NSEG * GSEG)      // 44976
#define LEN_F (BS_F + NROWS)            // 45104
#define ML_F  (LEN_F + NB)              // 45168
#define HST_F (ML_F + 4)                // 45172  h staging [BPC][32]
#define MB_F  (HST_F + BPC * 32)        // 45300  2 mbarriers (16B-aligned)
#define SM_FLOATS (MB_F + 8)            // 45308 (~181 KB)

__device__ __forceinline__ float sigf(float x)  { return 1.0f / (1.0f + __expf(-x)); }
__device__ __forceinline__ float tanha(float x) { return 2.0f / (1.0f + __expf(-2.0f * x)) - 1.0f; }

#define LDS2U64(a, b, addr) \
    asm volatile("ld.shared.v2.u64 {%0,%1}, [%2];" : "=l"(a), "=l"(b) : "r"(addr))
#define FMA2(acc, w, z) \
    asm volatile("fma.rn.f32x2 %0, %1, %2, %0;" : "+l"(acc) : "l"(w), "l"(z))

#define MBARRIER_INIT(mbar, cnt) \
    asm volatile("mbarrier.init.shared.b64 [%0], %1;" :: "r"(mbar), "r"(cnt) : "memory")

// cluster-scope acquire wait (HW-sleep)
#define MBAR_WAIT_CLUSTER(mbar, ph) do {                                            \
    uint32_t _m = (mbar), _p = (ph), _done;                                         \
    asm volatile("{\n\t.reg .pred p;\n\t"                                           \
        "mbarrier.try_wait.parity.acquire.cluster.shared::cta.b64 p, [%1], %2;\n\t" \
        "selp.b32 %0, 1, 0, p;\n\t}"                                                \
        : "=r"(_done) : "r"(_m), "r"(_p) : "memory");                               \
    if (!_done) {                                                                   \
        asm volatile("{\n\t.reg .pred P1;\n\t"                                      \
            "WL_%=:\n\t"                                                            \
            "mbarrier.try_wait.parity.acquire.cluster.shared::cta.b64 P1, [%0], %1, 0x989680;\n\t" \
            "@P1 bra.uni WD_%=;\n\t"                                                \
            "bra.uni WL_%=;\n\t"                                                    \
            "WD_%=:\n\t}"                                                           \
            :: "r"(_m), "r"(_p) : "memory");                                        \
    }                                                                               \
} while (0)

#define CLUSTER_SYNC() do { \
    asm volatile("barrier.cluster.arrive.aligned;" ::: "memory"); \
    asm volatile("barrier.cluster.wait.aligned;" ::: "memory"); \
} while (0)

__global__ void __launch_bounds__(NTHREADS, 1) __cluster_dims__(CSIZE, 1, 1)
lstm_dsmem_kernel(const int* __restrict__ x,        // [NB, NT]
                  const int* __restrict__ lengths,  // [NB]
                  const float* __restrict__ emb,    // [VOCAB, EMBD]
                  const float* __restrict__ W_ih,   // [4*HID, EMBD]
                  const float* __restrict__ W_hh,   // [4*HID, HID]
                  const float* __restrict__ b_ih,   // [4*HID]
                  const float* __restrict__ b_hh,   // [4*HID]
                  float* __restrict__ out)          // [NB, 1, HID]
{
    extern __shared__ float sm[];
    float* w_s  = sm + W_F;
    float* gp   = sm + GP_F;
    float* bs   = sm + BS_F;
    int* lenS   = (int*)(sm + LEN_F);
    int* mlS    = (int*)(sm + ML_F);
    float* hst  = sm + HST_F;               // [BPC][32] h staging

    const int tid = threadIdx.x;
    uint32_t usr;
    asm("mov.u32 %0, %%cluster_ctarank;" : "=r"(usr));
    const int us  = (int)usr;               // 0..7 (unit slice)
    const int bsl = blockIdx.x >> 3;        // 0..15 (batch group)
    const int u0  = us * UPC;
    const int bb0 = bsl * BPC;

    // ---- one-time staging: W rows (row r = g*32 + du), biases, lengths ----
    for (int idx = tid; idx < NROWS * KTOT; idx += NTHREADS) {
        int r = idx / KTOT;
        int k = idx - r * KTOT;
        int g = r >> 5, du = r & 31;
        int grow = g * HID + u0 + du;
        float v = (k < EMBD) ? W_ih[grow * EMBD + k]
                             : W_hh[grow * HID + (k - EMBD)];
        w_s[(r >> 2) * WRG + (r & 3) * WJ + k] = v;
    }
    if (tid < NROWS) {
        int g = tid >> 5, du = tid & 31;
        int grow = g * HID + u0 + du;
        bs[tid] = b_ih[grow] + b_hh[grow];
    }
    if (tid < NB) lenS[tid] = lengths[tid];
    __syncthreads();
    if (tid == 0) {
        int m = 1;
        for (int b = 0; b < NB; b++) m = max(m, lenS[b]);
        *mlS = m;
    }
    // zero h regions of BOTH z buffers (t=0 reads zeros)
    for (int i = tid; i < 2 * BPC * HID; i += NTHREADS) {
        int buf = i >= BPC * HID;
        int j = i - buf * BPC * HID;
        int b = j >> 8, u = j & 255;
        sm[Z_F + buf * ZBUF + b * ZPAD + EMBD + u] = 0.0f;
    }
    // gather xe(0) into buf 0
    if (tid < 8 * BPC) {
        int b = tid >> 3, q = tid & 7;
        int tok = x[(bb0 + b) * NT + 0];
        float4 v = ((const float4*)(emb + (size_t)tok * EMBD))[q];
        *(float4*)(sm + Z_F + b * ZPAD + q * 4) = v;
    }
    __syncthreads();
    const int maxlen = *mlS;

    // shared base for asm addressing
    uint32_t sb;
    asm("{ .reg .u64 t; cvta.to.shared.u64 t, %1; cvt.u32.u64 %0, t; }"
        : "=r"(sb) : "l"(sm));
    const uint32_t MB_B = sb + (uint32_t)(MB_F * 4);

    // init the two count-8 mbarriers; rendezvous before any DSMEM traffic
    if (tid == 0) {
        MBARRIER_INIT(MB_B + 0u, CSIZE);
        MBARRIER_INIT(MB_B + 8u, CSIZE);
    }
    __syncthreads();
    CLUSTER_SYNC();

    // mapa'd peer base addresses (z region and mbarriers), all 8 ranks
    uint32_t pz[CSIZE], pm[CSIZE];
    #pragma unroll
    for (int r = 0; r < CSIZE; r++) {
        asm("mapa.shared::cluster.u32 %0, %1, %2;"
            : "=r"(pz[r]) : "r"(sb + (uint32_t)(Z_F * 4)), "r"(r));
        asm("mapa.shared::cluster.u32 %0, %1, %2;"
            : "=r"(pm[r]) : "r"(MB_B), "r"(r));
    }

    // GEMM mapping: tid = seg*64 + rg*2 + bq
    const int seg = tid >> 6;                // 0..3
    const int rg  = (tid >> 1) & 31;         // rows 4rg..4rg+3
    const int bq  = tid & 1;                 // batches bq, bq+2
    const uint32_t wbase = sb + (uint32_t)(W_F + rg * WRG) * 4u;
    const uint32_t wk    = wbase + (uint32_t)(EMBD + seg * SEGK) * 4u;
    const uint32_t zA0   = sb + (uint32_t)(Z_F + bq * ZPAD) * 4u;       // buf0 base
    const uint32_t zB0   = zA0 + (uint32_t)(2 * ZPAD) * 4u;
    const uint32_t zkA0  = zA0 + (uint32_t)(EMBD + seg * SEGK) * 4u;
    const uint32_t zkB0  = zB0 + (uint32_t)(EMBD + seg * SEGK) * 4u;
    float* gpb = gp + seg * GSEG;

    // phase-2 mapping (tid < 128): unit u_l = tid>>2 (0..31), batch b2 = tid&3
    const int u_l = tid >> 2;
    const int b2  = tid & 3;
    const int bg  = bb0 + (b2 & 3);
    const int uu  = u0 + (u_l & 31);
    const int mylen = (tid < 128) ? lenS[bg] : 0;
    float c_r = 0.0f, h_r = 0.0f;

    // pusher/xe mapping (tid < 32): batch xb, quad xq
    const int xb = tid >> 3, xq = tid & 7;

    unsigned long long A[4][2];
    #pragma unroll
    for (int j = 0; j < 4; j++) { A[j][0] = 0ull; A[j][1] = 0ull; }

    // ---- prologue: seg0 accumulates W_ih . xe(0) from buf 0 ----
    if (seg == 0) {
        #pragma unroll
        for (int k = 0; k < EMBD; k += 4) {
            unsigned long long Z01a, Z23a, Z01b, Z23b;
            LDS2U64(Z01a, Z23a, zA0 + k * 4);
            LDS2U64(Z01b, Z23b, zB0 + k * 4);
            #pragma unroll
            for (int j = 0; j < 4; j++) {
                unsigned long long W01, W23;
                LDS2U64(W01, W23, wbase + (uint32_t)(j * WJ + k) * 4u);
                FMA2(A[j][0], W01, Z01a); FMA2(A[j][0], W23, Z23a);
                FMA2(A[j][1], W01, Z01b); FMA2(A[j][1], W23, Z23b);
            }
        }
    }

    int ph0 = 0, ph1 = 0;    // parity cursors for mbar[0], mbar[1]

    for (int t = 0; t < maxlen; t++) {
        const uint32_t zbo = (t & 1) ? (uint32_t)(ZBUF * 4) : 0u;

        // ---- wait for all 8 peers' h(t-1) pushes (local mbar, HW-sleep) ----
        if (t > 0) {
            if (t & 1) { MBAR_WAIT_CLUSTER(MB_B + 8u, (uint32_t)ph1); ph1 ^= 1; }
            else       { MBAR_WAIT_CLUSTER(MB_B + 0u, (uint32_t)ph0); ph0 ^= 1; }
        }

        // ---- partial acc += W_hh . h(t-1) over my 64-k segment (buf t&1) ----
        {
            const uint32_t zkA = zkA0 + zbo;
            const uint32_t zkB = zkB0 + zbo;
            #pragma unroll 4
            for (int k = 0; k < SEGK; k += 4) {
                unsigned long long Z01a, Z23a, Z01b, Z23b;
                LDS2U64(Z01a, Z23a, zkA + k * 4);
                LDS2U64(Z01b, Z23b, zkB + k * 4);
                #pragma unroll
                for (int j = 0; j < 4; j++) {
                    unsigned long long W01, W23;
                    LDS2U64(W01, W23, wk + (uint32_t)(j * WJ + k) * 4u);
                    FMA2(A[j][0], W01, Z01a); FMA2(A[j][0], W23, Z23a);
                    FMA2(A[j][1], W01, Z01b); FMA2(A[j][1], W23, Z23b);
                }
            }
        }
        // write partial gate sums (lo+hi of k-split accumulators)
        #pragma unroll
        for (int j = 0; j < 4; j++) {
            float ga = __uint_as_float((uint32_t)A[j][0]) +
                       __uint_as_float((uint32_t)(A[j][0] >> 32));
            float gb = __uint_as_float((uint32_t)A[j][1]) +
                       __uint_as_float((uint32_t)(A[j][1] >> 32));
            gpb[(4 * rg + j) * GSTR + bq]     = ga;
            gpb[(4 * rg + j) * GSTR + bq + 2] = gb;
        }
        __syncthreads();

        // ---- phase 2 (tid < 128): reduce 4 partials + bias, activations ----
        if (tid < 128) {
            float gate[4];
            #pragma unroll
            for (int g = 0; g < 4; g++) {
                int r = g * UPC + u_l;
                float s = bs[r];
                #pragma unroll
                for (int sg = 0; sg < NSEG; sg++)
                    s += gp[sg * GSEG + r * GSTR + b2];
                gate[g] = s;
            }
            float iv = sigf(gate[0]), fv = sigf(gate[1]);
            float gv = tanha(gate[2]), ov = sigf(gate[3]);
            float cn = fmaf(fv, c_r, iv * gv);
            float hn = ov * tanha(cn);
            if (t < mylen) { c_r = cn; h_r = hn; }
            hst[b2 * 32 + u_l] = h_r;            // local staging tile
        }
        __syncthreads();   // staging complete CTA-wide

        if (t + 1 < maxlen) {
            const int buf1 = (t + 1) & 1;
            // ---- push h(t): warp 0, 8 vectorized remote stores per lane ----
            if (tid < 32) {
                float4 hv = *(const float4*)(hst + xb * 32 + xq * 4);
                uint32_t off = (uint32_t)((buf1 * ZBUF + xb * ZPAD + EMBD + u0 + xq * 4) * 4);
                #pragma unroll
                for (int r = 0; r < CSIZE; r++) {
                    asm volatile("st.shared::cluster.v4.f32 [%0], {%1,%2,%3,%4};"
                                 :: "r"(pz[r] + off),
                                    "f"(hv.x), "f"(hv.y), "f"(hv.z), "f"(hv.w)
                                 : "memory");
                }
                __syncwarp();
                // ---- notify: one remote count-arrive per peer (release.cluster) ----
                if (tid < CSIZE) {
                    asm volatile("mbarrier.arrive.release.cluster.shared::cluster.b64 _, [%0];"
                                 :: "r"(pm[tid] + (uint32_t)(buf1 * 8)) : "memory");
                }
                // ---- xe(t+1) gather into buf1 (same warp, after notify) ----
                int tok = x[(bb0 + xb) * NT + (t + 1)];
                float4 v = ((const float4*)(emb + (size_t)tok * EMBD))[xq];
                *(float4*)(sm + Z_F + buf1 * ZBUF + xb * ZPAD + xq * 4) = v;
            }
            __syncthreads();
            // ---- reset partials; seg0 folds in the xe GEMM for t+1 ----
            #pragma unroll
            for (int j = 0; j < 4; j++) { A[j][0] = 0ull; A[j][1] = 0ull; }
            if (seg == 0) {
                const uint32_t zbo1 = buf1 ? (uint32_t)(ZBUF * 4) : 0u;
                const uint32_t zxA = zA0 + zbo1;
                const uint32_t zxB = zB0 + zbo1;
                #pragma unroll
                for (int k = 0; k < EMBD; k += 4) {
                    unsigned long long Z01a, Z23a, Z01b, Z23b;
                    LDS2U64(Z01a, Z23a, zxA + k * 4);
                    LDS2U64(Z01b, Z23b, zxB + k * 4);
                    #pragma unroll
                    for (int j = 0; j < 4; j++) {
                        unsigned long long W01, W23;
                        LDS2U64(W01, W23, wbase + (uint32_t)(j * WJ + k) * 4u);
                        FMA2(A[j][0], W01, Z01a); FMA2(A[j][0], W23, Z23a);
                        FMA2(A[j][1], W01, Z01b); FMA2(A[j][1], W23, Z23b);
                    }
                }
            }
        }
    }

    // final frozen h == reference out[:, -1, :]
    if (tid < 128) out[bg * HID + uu] = h_r;

    // no CTA exits while cluster peers may still interact
    CLUSTER_SYNC();
}

extern "C" void kernel_launch(void* const* d_in, const int* in_sizes, int n_in,
                              void* d_out, int out_size) {
    const int*   x       = (const int*)d_in[0];
    const int*   lengths = (const int*)d_in[1];
    const float* emb     = (const float*)d_in[2];
    const float* W_ih    = (const float*)d_in[3];
    const float* W_hh    = (const float*)d_in[4];
    const float* b_ih    = (const float*)d_in[5];
    const float* b_hh    = (const float*)d_in[6];
    float* out = (float*)d_out;

    const int smem_bytes = SM_FLOATS * (int)sizeof(float) + 32;

    cudaFuncSetAttribute(lstm_dsmem_kernel,
                         cudaFuncAttributeMaxDynamicSharedMemorySize, smem_bytes);

    lstm_dsmem_kernel<<<NCTA, NTHREADS, smem_bytes>>>(
        x, lengths, emb, W_ih, W_hh, b_ih, b_hh, out);
}